// round 6
// baseline (speedup 1.0000x reference)
#include <cuda_runtime.h>
#include <stdint.h>

#define BB 4
#define NN 4096
#define NC 80
#define ST 85
#define IOU_TH 0.45f
#define CAPB 128
#define NBINS 1024
#define NBLK 128
#define NTHR 1024
#define TPB 5            // NMS tasks per block (640 / 128)
#define FULL 0xffffffffu
#define SLOTS (NC*CAPB)  // 10240 clean slots per image
#define ROWS_PER_BLK 256
#define TILE_FLOATS (ROWS_PER_BLK*ST)          // 21760
#define TILE_F4 (TILE_FLOATS/4)                // 5440
#define DYN_SMEM (TILE_FLOATS*4)               // 87040 bytes

// ---------------- scratch (device globals; no allocation allowed) ----------------
__device__ unsigned long long g_bkey [2*BB*NC*CAPB]; // (confbits<<20)|((4095-idx)<<8)|slot
__device__ float4             g_bobox[2*BB*NC*CAPB]; // offset boxes (cls*4096 added)
__device__ float4             g_bnbox[2*BB*NC*CAPB]; // normalized boxes (/640)
__device__ int                g_cnt  [2*BB*NC];      // bin counters (consumer-reset)

__device__ int                g_kccnt[BB*NC];
__device__ unsigned long long g_kckey[BB*NC*CAPB];   // (confbits<<12)|(4095-idx)
__device__ float4             g_kcnbox[BB*NC*CAPB];
__device__ float              g_kcarea[BB*NC*CAPB];
__device__ int                g_pcnt [BB*NC];
__device__ float4             g_pnbox[BB*NC*CAPB];
__device__ float              g_parea[BB*NC*CAPB];

__device__ float             g_part[NBLK];
__device__ unsigned          g_bar_cnt;
__device__ volatile unsigned g_bar_gen;

__device__ __forceinline__ void grid_barrier() {
    __syncthreads();
    if (threadIdx.x == 0) {
        unsigned gen = g_bar_gen;
        __threadfence();
        if (atomicAdd(&g_bar_cnt, 1u) == NBLK - 1) {
            g_bar_cnt = 0;
            __threadfence();
            g_bar_gen = gen + 1;
        } else {
            while (g_bar_gen == gen) { }   // tight L2 poll, 1 thread/block
        }
        __threadfence();
    }
    __syncthreads();
}

__global__ void __launch_bounds__(NTHR, 1) k_fused(const float* __restrict__ in0,
                                                   const float* __restrict__ in1,
                                                   float* __restrict__ out) {
    extern __shared__ float s_raw[];                 // 256 rows x 85 floats (phase A only)
    __shared__ unsigned long long skey[TPB][CAPB];
    __shared__ int   s_pre[NBINS];
    __shared__ float s_red[NTHR];
    __shared__ int   s_scnt[NC];
    __shared__ int   s_wsum[32];
    __shared__ unsigned long long s_bb[64];
    __shared__ int   s_T, s_bound, s_bbn;

    const int tid  = threadIdx.x;
    const int lane = tid & 31;
    const int wb   = tid >> 5;

    // ================= Phase A: stream tile to smem; 4-lane-per-box decode ==========
    {
        const int set      = blockIdx.x >> 6;            // 0..63 clean, 64..127 patch
        const int tilebase = (blockIdx.x & 63) * ROWS_PER_BLK;
        const float4* src4 = (const float4*)((set ? in1 : in0) + (size_t)tilebase * ST);
        float4* d4 = (float4*)s_raw;

        #pragma unroll
        for (int t = 0; t < 6; t++) {                    // 6*1024 >= 5440
            int i = tid + t * NTHR;
            if (i < TILE_F4) d4[i] = __ldg(src4 + i);
        }
        __syncthreads();

        const int g  = lane >> 2;                        // box group 0..7
        const int lg = lane & 3;                         // lane in group
        const int row = (wb << 3) | g;
        const float* rp = s_raw + row * ST;
        float obj = rp[4];

        float bv = -1e30f; int bc = 0x7fffffff;
        #pragma unroll
        for (int t = 0; t < 20; t++) {
            int c = lg + (t << 2);                       // 20 classes per lane
            float s = rp[5 + c] * obj;                   // ref op order: cls * obj
            if (s > bv) { bv = s; bc = c; }              // strict > keeps first in-lane
        }
        // 2-level xor reduce within the 4-lane group (value desc, index asc)
        #pragma unroll
        for (int o = 1; o <= 2; o <<= 1) {
            float ov = __shfl_xor_sync(FULL, bv, o);
            int   oi = __shfl_xor_sync(FULL, bc, o);
            if (ov > bv || (ov == bv && oi < bc)) { bv = ov; bc = oi; }
        }

        if (lg == 0) {                                   // 8 parallel writers per warp
            int r = tilebase + row;                      // b*NN + n within set
            float th = set ? 0.001f : 0.25f;
            if (obj > th && bv > th) {
                float cx = rp[0], cy = rp[1], w = rp[2], h = rp[3];
                float hw = w * 0.5f, hh = h * 0.5f;
                float x1 = cx - hw, y1 = cy - hh, x2 = cx + hw, y2 = cy + hh;
                float off = (float)bc * 4096.0f;
                int b = r >> 12, idx = r & (NN - 1);
                int bin = (set * BB + b) * NC + bc;
                int slot = atomicAdd(&g_cnt[bin], 1);
                if (slot < CAPB) {
                    int a = bin * CAPB + slot;
                    float4 ob; ob.x = x1 + off; ob.y = y1 + off; ob.z = x2 + off; ob.w = y2 + off;
                    float4 nb; nb.x = __fdiv_rn(x1, 640.0f); nb.y = __fdiv_rn(y1, 640.0f);
                               nb.z = __fdiv_rn(x2, 640.0f); nb.w = __fdiv_rn(y2, 640.0f);
                    g_bobox[a] = ob; g_bnbox[a] = nb;
                    g_bkey [a] = ((unsigned long long)__float_as_uint(bv) << 20)
                               | ((unsigned long long)(4095 - idx) << 8)
                               | (unsigned long long)slot;
                }
            }
        }
    }
    grid_barrier();

    // ================= Phase B: per-(set,img,class) sort + greedy NMS ===============
    if (wb < TPB) {
        int task = blockIdx.x * TPB + wb;            // 0..639
        int c   = task % NC;
        int sb  = task / NC;
        int set = sb >> 2, b = sb & 3;
        int bin = sb * NC + c;
        int gbase = bin * CAPB;

        int K = min(g_cnt[bin], CAPB);
        if (lane == 0) g_cnt[bin] = 0;

        for (int i = lane; i < K; i += 32) skey[wb][i] = g_bkey[gbase + i];
        int P = 1; while (P < K) P <<= 1;
        for (int i = K + lane; i < P; i += 32) skey[wb][i] = 0ull;
        __syncwarp();

        for (int kk = 2; kk <= P; kk <<= 1) {
            for (int j = kk >> 1; j; j >>= 1) {
                for (int i = lane; i < P; i += 32) {
                    int x = i ^ j;
                    if (x > i) {
                        unsigned long long a = skey[wb][i], b2 = skey[wb][x];
                        bool up = ((i & kk) == 0);
                        if (up ? (a < b2) : (a > b2)) { skey[wb][i] = b2; skey[wb][x] = a; }
                    }
                }
                __syncwarp();
            }
        }

        float4 bx[4]; float ar[4]; unsigned sup = 0;
        #pragma unroll
        for (int q = 0; q < 4; q++) {
            int pos = q * 32 + lane;
            if (pos < K) {
                int slot = (int)(skey[wb][pos] & 0xFFull);
                float4 bo = g_bobox[gbase + slot];
                bx[q] = bo;
                ar[q] = (bo.z - bo.x) * (bo.w - bo.y);
            } else {
                bx[q] = make_float4(0.f, 0.f, 0.f, 0.f); ar[q] = 0.f;
                sup |= 1u << q;
            }
        }
        __syncwarp();

        #pragma unroll
        for (int q = 0; q < 4; q++) {
            if (q * 32 >= K) break;
            for (int src = 0; src < 32; src++) {
                int i = q * 32 + src;
                if (i >= K) break;
                unsigned sall = __shfl_sync(FULL, sup, src);
                float bix = __shfl_sync(FULL, bx[q].x, src);
                float biy = __shfl_sync(FULL, bx[q].y, src);
                float biz = __shfl_sync(FULL, bx[q].z, src);
                float biw = __shfl_sync(FULL, bx[q].w, src);
                float ai  = __shfl_sync(FULL, ar[q],  src);
                if (!((sall >> q) & 1)) {
                    #pragma unroll
                    for (int p = 0; p < 4; p++) {
                        if (p < q) continue;
                        int j = p * 32 + lane;
                        if (j > i && j < K && !((sup >> p) & 1)) {
                            float lx = fmaxf(bix, bx[p].x), ly = fmaxf(biy, bx[p].y);
                            float rx = fminf(biz, bx[p].z), ry = fminf(biw, bx[p].w);
                            float wv = fmaxf(rx - lx, 0.0f), hv = fmaxf(ry - ly, 0.0f);
                            float inter = wv * hv;
                            float uni = ai + ar[p] - inter;
                            if (__fdiv_rn(inter, uni) > IOU_TH) sup |= 1u << p;
                        }
                    }
                }
            }
        }

        int m = 0;
        #pragma unroll
        for (int q = 0; q < 4; q++) {
            int pos = q * 32 + lane;
            bool kp = (pos < K) && !((sup >> q) & 1);
            unsigned bal = __ballot_sync(FULL, kp);
            if (kp) {
                int o = m + __popc(bal & ((1u << lane) - 1u));
                unsigned long long key = skey[wb][pos];
                int slot = (int)(key & 0xFFull);
                float4 nb = g_bnbox[gbase + slot];
                float na = (nb.z - nb.x) * (nb.w - nb.y);
                int dst = (b * NC + c) * CAPB + o;
                if (set == 0) {
                    g_kckey [dst] = key >> 8;        // (confbits<<12)|(4095-idx)
                    g_kcnbox[dst] = nb; g_kcarea[dst] = na;
                } else {
                    g_pnbox[dst] = nb; g_parea[dst] = na;
                }
            }
            m += __popc(bal);
        }
        if (lane == 0) { if (set == 0) g_kccnt[b * NC + c] = m; else g_pcnt[b * NC + c] = m; }
    }
    grid_barrier();

    // ================= Phase C: cap@1000 (hist rank) + tm + partials ================
    {
        int b    = blockIdx.x & 3;
        int part = blockIdx.x >> 2;                  // 0..31; only parts 0..9 hold slots

        if (part >= 10) {
            if (tid == 0) g_part[blockIdx.x] = 0.0f; // idle block: contribute zero
        } else {
            if (tid < NC) s_scnt[tid] = g_kccnt[b * NC + tid];
            s_pre[tid] = 0;
            __syncthreads();
            if (tid == 0) {
                int t = 0;
                #pragma unroll
                for (int c = 0; c < NC; c++) t += s_scnt[c];
                s_T = t; s_bound = -1; s_bbn = 0;
            }

            // prefetch this thread's 10 strided slot keys (MLP=10, reused twice)
            unsigned long long pk[10]; bool ph[10];
            #pragma unroll
            for (int t = 0; t < 10; t++) {
                int s = tid + t * NTHR;              // < 10240
                int c = s >> 7, i = s & (CAPB - 1);
                ph[t] = i < s_scnt[c];
                pk[t] = ph[t] ? g_kckey[(b * NC + c) * CAPB + i] : 0ull;
            }
            __syncthreads();
            int T = s_T;

            // histogram
            #pragma unroll
            for (int t = 0; t < 10; t++) {
                if (ph[t]) {
                    float cf = __uint_as_float((unsigned)(pk[t] >> 12));
                    int bn = min(max((int)(cf * 1024.0f), 0), NBINS - 1);
                    atomicAdd(&s_pre[bn], 1);
                }
            }
            __syncthreads();

            // two-level shuffle scan over 1024 bins (1 bin/thread)
            {
                int x = s_pre[tid];
                int v = x;
                #pragma unroll
                for (int o = 1; o < 32; o <<= 1) {
                    int y = __shfl_up_sync(FULL, v, o);
                    if (lane >= o) v += y;
                }
                if (lane == 31) s_wsum[wb] = v;
                __syncthreads();
                if (wb == 0) {
                    int w = s_wsum[lane];
                    #pragma unroll
                    for (int o = 1; o < 32; o <<= 1) {
                        int y = __shfl_up_sync(FULL, w, o);
                        if (lane >= o) w += y;
                    }
                    s_wsum[lane] = w;
                }
                __syncthreads();
                int incl = v + (wb ? s_wsum[wb - 1] : 0);
                s_pre[tid] = incl;
                int S = x, A = T - incl;
                if (T > 1000 && S > 0 && A < 1000 && A + S > 1000) s_bound = tid;
            }
            __syncthreads();
            int bd = s_bound;
            if (bd >= 0) {
                #pragma unroll
                for (int t = 0; t < 10; t++) {
                    if (ph[t]) {
                        float cf = __uint_as_float((unsigned)(pk[t] >> 12));
                        int bn = min(max((int)(cf * 1024.0f), 0), NBINS - 1);
                        if (bn == bd) {
                            int o = atomicAdd(&s_bbn, 1);
                            if (o < 64) s_bb[o] = pk[t];
                        }
                    }
                }
            }
            __syncthreads();
            int nbb = min(s_bbn, 64);
            bool bbOv = s_bbn > 64;

            // main: one slot per thread
            float psum = 0.0f;
            int s = part * NTHR + tid;
            {
                int c = s >> 7, i = s & (CAPB - 1);
                if (i < s_scnt[c]) {
                    int gb = (b * NC + c) * CAPB + i;
                    unsigned long long mykey = g_kckey[gb];
                    float cf = __uint_as_float((unsigned)(mykey >> 12));
                    int bn = min(max((int)(cf * 1024.0f), 0), NBINS - 1);
                    int incl = s_pre[bn], excl = bn ? s_pre[bn - 1] : 0;
                    int S = incl - excl, A = T - incl;
                    bool keep;
                    if (T <= 1000)          keep = true;
                    else if (A >= 1000)     keep = false;
                    else if (A + S <= 1000) keep = true;
                    else {
                        int rin = 0;
                        if (!bbOv) {
                            for (int q = 0; q < nbb; q++) rin += (s_bb[q] > mykey);
                        } else {  // practically impossible fallback: exact in-bin rank
                            for (int s2 = 0; s2 < SLOTS; s2++) {
                                int c2 = s2 >> 7, i2 = s2 & (CAPB - 1);
                                if (i2 < s_scnt[c2]) {
                                    unsigned long long k2 = g_kckey[(b * NC + c2) * CAPB + i2];
                                    float cf2 = __uint_as_float((unsigned)(k2 >> 12));
                                    int bn2 = min(max((int)(cf2 * 1024.0f), 0), NBINS - 1);
                                    if (bn2 == bn && k2 > mykey) rin++;
                                }
                            }
                        }
                        keep = (A + rin) < 1000;
                    }
                    if (keep) {
                        float4 bxc = g_kcnbox[gb]; float ab = g_kcarea[gb];
                        int Kp = g_pcnt[b * NC + c]; int lb = (b * NC + c) * CAPB;
                        float tmv = 0.0f;
                        for (int mm = 0; mm < Kp; mm++) {
                            float4 pj = g_pnbox[lb + mm];
                            float lx = fmaxf(bxc.x, pj.x), ly = fmaxf(bxc.y, pj.y);
                            float rx = fminf(bxc.z, pj.z), ry = fminf(bxc.w, pj.w);
                            float wv = fmaxf(rx - lx, 0.0f), hv = fmaxf(ry - ly, 0.0f);
                            float inter = wv * hv;
                            float uni = g_parea[lb + mm] + ab - inter;
                            tmv = fmaxf(tmv, __fdiv_rn(inter, uni));
                        }
                        psum = tmv;
                    }
                }
            }
            // block reduce
            {
                #pragma unroll
                for (int o = 16; o; o >>= 1) psum += __shfl_down_sync(FULL, psum, o);
                if (lane == 0) s_red[wb] = psum;
                __syncthreads();
                if (wb == 0) {
                    float v = s_red[lane];
                    #pragma unroll
                    for (int o = 16; o; o >>= 1) v += __shfl_down_sync(FULL, v, o);
                    if (lane == 0) g_part[blockIdx.x] = v;
                }
            }
        }
    }
    grid_barrier();

    // ================= Phase D: final scalar (block 0, fixed-order) =================
    if (blockIdx.x == 0) {
        if (tid < BB * NC) s_pre[tid] = g_kccnt[tid];
        float v = (tid < NBLK) ? g_part[tid] : 0.0f;
        #pragma unroll
        for (int o = 16; o; o >>= 1) v += __shfl_down_sync(FULL, v, o);
        if (lane == 0) s_red[wb] = v;
        __syncthreads();
        if (tid == 0) {
            float num = 0.0f;
            #pragma unroll
            for (int w = 0; w < 4; w++) num += s_red[w];
            int den = 0;
            for (int b = 0; b < BB; b++) {
                int t = 0;
                for (int c = 0; c < NC; c++) t += s_pre[b * NC + c];
                den += min(t, 1000);
            }
            out[0] = (den > 0) ? (1.0f - __fdiv_rn(num, (float)den)) : 1.0f;
        }
    }
}

// ---------------- launch ----------------
extern "C" void kernel_launch(void* const* d_in, const int* in_sizes, int n_in,
                              void* d_out, int out_size) {
    const float* c = (const float*)d_in[0];
    const float* p = (const float*)d_in[1];
    float* out = (float*)d_out;
    cudaFuncSetAttribute(k_fused, cudaFuncAttributeMaxDynamicSharedMemorySize, DYN_SMEM);
    k_fused<<<NBLK, NTHR, DYN_SMEM>>>(c, p, out);
}

// round 9
// speedup vs baseline: 1.0044x; 1.0044x over previous
#include <cuda_runtime.h>
#include <stdint.h>

#define BB 4
#define NN 4096
#define NC 80
#define ST 85
#define IOU_TH 0.45f
#define CAPB 128
#define NBINS 1024
#define NBLK 128
#define NTHR 1024
#define TPB 5            // NMS tasks per block (640 / 128)
#define FULL 0xffffffffu
#define SLOTS (NC*CAPB)  // 10240 clean slots per image
#define ROWS_PER_BLK 256
#define TILE_FLOATS (ROWS_PER_BLK*ST)          // 21760
#define TILE_F4 (TILE_FLOATS/4)                // 5440
#define DYN_SMEM (TILE_FLOATS*4)               // 87040 bytes

// ---------------- scratch (device globals; no allocation allowed) ----------------
__device__ unsigned long long g_bkey [2*BB*NC*CAPB]; // (confbits<<20)|((4095-idx)<<8)|slot
__device__ float4             g_bobox[2*BB*NC*CAPB]; // offset boxes (cls*4096 added)
__device__ float4             g_bnbox[2*BB*NC*CAPB]; // normalized boxes (/640)
__device__ int                g_cnt  [2*BB*NC];      // bin counters (consumer-reset)

__device__ int                g_kccnt[BB*NC];
__device__ unsigned long long g_kckey[BB*NC*CAPB];   // (confbits<<12)|(4095-idx)
__device__ float4             g_kcnbox[BB*NC*CAPB];
__device__ float              g_kcarea[BB*NC*CAPB];
__device__ int                g_pcnt [BB*NC];
__device__ float4             g_pnbox[BB*NC*CAPB];
__device__ float              g_parea[BB*NC*CAPB];

__device__ float             g_part[NBLK];
__device__ unsigned          g_bar_cnt;
__device__ volatile unsigned g_bar_gen;
__device__ unsigned          g_tick;                 // phase-D ticket (self-resetting)

__device__ __forceinline__ void grid_barrier() {
    __syncthreads();
    if (threadIdx.x == 0) {
        unsigned gen = g_bar_gen;
        __threadfence();
        if (atomicAdd(&g_bar_cnt, 1u) == NBLK - 1) {
            g_bar_cnt = 0;
            __threadfence();
            g_bar_gen = gen + 1;
        } else {
            while (g_bar_gen == gen) { }   // tight L2 poll, 1 thread/block
        }
        __threadfence();
    }
    __syncthreads();
}

__global__ void __launch_bounds__(NTHR, 1) k_fused(const float* __restrict__ in0,
                                                   const float* __restrict__ in1,
                                                   float* __restrict__ out) {
    extern __shared__ float s_raw[];                 // 256 rows x 85 floats (phase A only)
    __shared__ unsigned long long skey[TPB][CAPB];
    __shared__ int   s_pre[NBINS];
    __shared__ float s_red[NTHR];
    __shared__ int   s_scnt[NC];
    __shared__ int   s_wsum[32];
    __shared__ unsigned long long s_bb[64];
    __shared__ int   s_T, s_bound, s_bbn, s_last;

    const int tid  = threadIdx.x;
    const int lane = tid & 31;
    const int wb   = tid >> 5;

    // ================= Phase A: stream tile to smem; 4-lane-per-box decode ==========
    {
        const int set      = blockIdx.x >> 6;            // 0..63 clean, 64..127 patch
        const int tilebase = (blockIdx.x & 63) * ROWS_PER_BLK;
        const float4* src4 = (const float4*)((set ? in1 : in0) + (size_t)tilebase * ST);
        float4* d4 = (float4*)s_raw;

        #pragma unroll
        for (int t = 0; t < 6; t++) {                    // 6*1024 >= 5440
            int i = tid + t * NTHR;
            if (i < TILE_F4) d4[i] = __ldg(src4 + i);
        }
        __syncthreads();

        const int g  = lane >> 2;                        // box group 0..7
        const int lg = lane & 3;                         // lane in group
        const int row = (wb << 3) | g;
        const float* rp = s_raw + row * ST;
        float obj = rp[4];

        float bv = -1e30f; int bc = 0x7fffffff;
        #pragma unroll
        for (int t = 0; t < 20; t++) {
            int c = lg + (t << 2);                       // 20 classes per lane
            float s = rp[5 + c] * obj;                   // ref op order: cls * obj
            if (s > bv) { bv = s; bc = c; }              // strict > keeps first in-lane
        }
        // 2-level xor reduce within the 4-lane group (value desc, index asc)
        #pragma unroll
        for (int o = 1; o <= 2; o <<= 1) {
            float ov = __shfl_xor_sync(FULL, bv, o);
            int   oi = __shfl_xor_sync(FULL, bc, o);
            if (ov > bv || (ov == bv && oi < bc)) { bv = ov; bc = oi; }
        }

        if (lg == 0) {                                   // 8 parallel writers per warp
            int r = tilebase + row;                      // b*NN + n within set
            float th = set ? 0.001f : 0.25f;
            if (obj > th && bv > th) {
                float cx = rp[0], cy = rp[1], w = rp[2], h = rp[3];
                float hw = w * 0.5f, hh = h * 0.5f;
                float x1 = cx - hw, y1 = cy - hh, x2 = cx + hw, y2 = cy + hh;
                float off = (float)bc * 4096.0f;
                int b = r >> 12, idx = r & (NN - 1);
                int bin = (set * BB + b) * NC + bc;
                int slot = atomicAdd(&g_cnt[bin], 1);
                if (slot < CAPB) {
                    int a = bin * CAPB + slot;
                    float4 ob; ob.x = x1 + off; ob.y = y1 + off; ob.z = x2 + off; ob.w = y2 + off;
                    float4 nb; nb.x = __fdiv_rn(x1, 640.0f); nb.y = __fdiv_rn(y1, 640.0f);
                               nb.z = __fdiv_rn(x2, 640.0f); nb.w = __fdiv_rn(y2, 640.0f);
                    g_bobox[a] = ob; g_bnbox[a] = nb;
                    g_bkey [a] = ((unsigned long long)__float_as_uint(bv) << 20)
                               | ((unsigned long long)(4095 - idx) << 8)
                               | (unsigned long long)slot;
                }
            }
        }
    }
    grid_barrier();

    // ================= Phase B: per-(set,img,class) sort + greedy NMS ===============
    if (wb < TPB) {
        int task = blockIdx.x * TPB + wb;            // 0..639
        int c   = task % NC;
        int sb  = task / NC;
        int set = sb >> 2, b = sb & 3;
        int bin = sb * NC + c;
        int gbase = bin * CAPB;

        int K = min(g_cnt[bin], CAPB);
        if (lane == 0) g_cnt[bin] = 0;

        for (int i = lane; i < K; i += 32) skey[wb][i] = g_bkey[gbase + i];
        int P = 1; while (P < K) P <<= 1;
        for (int i = K + lane; i < P; i += 32) skey[wb][i] = 0ull;
        __syncwarp();

        for (int kk = 2; kk <= P; kk <<= 1) {
            for (int j = kk >> 1; j; j >>= 1) {
                for (int i = lane; i < P; i += 32) {
                    int x = i ^ j;
                    if (x > i) {
                        unsigned long long a = skey[wb][i], b2 = skey[wb][x];
                        bool up = ((i & kk) == 0);
                        if (up ? (a < b2) : (a > b2)) { skey[wb][i] = b2; skey[wb][x] = a; }
                    }
                }
                __syncwarp();
            }
        }

        float4 bx[4]; float ar[4]; unsigned sup = 0;
        #pragma unroll
        for (int q = 0; q < 4; q++) {
            int pos = q * 32 + lane;
            if (pos < K) {
                int slot = (int)(skey[wb][pos] & 0xFFull);
                float4 bo = g_bobox[gbase + slot];
                bx[q] = bo;
                ar[q] = (bo.z - bo.x) * (bo.w - bo.y);
            } else {
                bx[q] = make_float4(0.f, 0.f, 0.f, 0.f); ar[q] = 0.f;
                sup |= 1u << q;
            }
        }
        __syncwarp();

        #pragma unroll
        for (int q = 0; q < 4; q++) {
            if (q * 32 >= K) break;
            for (int src = 0; src < 32; src++) {
                int i = q * 32 + src;
                if (i >= K) break;
                unsigned sall = __shfl_sync(FULL, sup, src);
                float bix = __shfl_sync(FULL, bx[q].x, src);
                float biy = __shfl_sync(FULL, bx[q].y, src);
                float biz = __shfl_sync(FULL, bx[q].z, src);
                float biw = __shfl_sync(FULL, bx[q].w, src);
                float ai  = __shfl_sync(FULL, ar[q],  src);
                if (!((sall >> q) & 1)) {
                    #pragma unroll
                    for (int p = 0; p < 4; p++) {
                        if (p < q) continue;
                        int j = p * 32 + lane;
                        if (j > i && j < K && !((sup >> p) & 1)) {
                            float lx = fmaxf(bix, bx[p].x), ly = fmaxf(biy, bx[p].y);
                            float rx = fminf(biz, bx[p].z), ry = fminf(biw, bx[p].w);
                            float wv = fmaxf(rx - lx, 0.0f), hv = fmaxf(ry - ly, 0.0f);
                            float inter = wv * hv;
                            float uni = ai + ar[p] - inter;
                            if (__fdiv_rn(inter, uni) > IOU_TH) sup |= 1u << p;
                        }
                    }
                }
            }
        }

        int m = 0;
        #pragma unroll
        for (int q = 0; q < 4; q++) {
            int pos = q * 32 + lane;
            bool kp = (pos < K) && !((sup >> q) & 1);
            unsigned bal = __ballot_sync(FULL, kp);
            if (kp) {
                int o = m + __popc(bal & ((1u << lane) - 1u));
                unsigned long long key = skey[wb][pos];
                int slot = (int)(key & 0xFFull);
                float4 nb = g_bnbox[gbase + slot];
                float na = (nb.z - nb.x) * (nb.w - nb.y);
                int dst = (b * NC + c) * CAPB + o;
                if (set == 0) {
                    g_kckey [dst] = key >> 8;        // (confbits<<12)|(4095-idx)
                    g_kcnbox[dst] = nb; g_kcarea[dst] = na;
                } else {
                    g_pnbox[dst] = nb; g_parea[dst] = na;
                }
            }
            m += __popc(bal);
        }
        if (lane == 0) { if (set == 0) g_kccnt[b * NC + c] = m; else g_pcnt[b * NC + c] = m; }
    }
    grid_barrier();

    // ================= Phase C: cap@1000 (hist rank) + tm + partials ================
    {
        int b    = blockIdx.x & 3;
        int part = blockIdx.x >> 2;                  // 0..31; only parts 0..9 hold slots

        if (part >= 10) {
            if (tid == 0) g_part[blockIdx.x] = 0.0f; // idle block: contribute zero
        } else {
            if (tid < NC) s_scnt[tid] = g_kccnt[b * NC + tid];
            s_pre[tid] = 0;
            __syncthreads();
            if (tid == 0) {
                int t = 0;
                #pragma unroll
                for (int c = 0; c < NC; c++) t += s_scnt[c];
                s_T = t; s_bound = -1; s_bbn = 0;
            }

            // prefetch this thread's 10 strided slot keys (MLP=10, reused twice)
            unsigned long long pk[10]; bool ph[10];
            #pragma unroll
            for (int t = 0; t < 10; t++) {
                int s = tid + t * NTHR;              // < 10240
                int c = s >> 7, i = s & (CAPB - 1);
                ph[t] = i < s_scnt[c];
                pk[t] = ph[t] ? g_kckey[(b * NC + c) * CAPB + i] : 0ull;
            }
            __syncthreads();
            int T = s_T;

            // histogram
            #pragma unroll
            for (int t = 0; t < 10; t++) {
                if (ph[t]) {
                    float cf = __uint_as_float((unsigned)(pk[t] >> 12));
                    int bn = min(max((int)(cf * 1024.0f), 0), NBINS - 1);
                    atomicAdd(&s_pre[bn], 1);
                }
            }
            __syncthreads();

            // two-level shuffle scan over 1024 bins (1 bin/thread)
            {
                int x = s_pre[tid];
                int v = x;
                #pragma unroll
                for (int o = 1; o < 32; o <<= 1) {
                    int y = __shfl_up_sync(FULL, v, o);
                    if (lane >= o) v += y;
                }
                if (lane == 31) s_wsum[wb] = v;
                __syncthreads();
                if (wb == 0) {
                    int w = s_wsum[lane];
                    #pragma unroll
                    for (int o = 1; o < 32; o <<= 1) {
                        int y = __shfl_up_sync(FULL, w, o);
                        if (lane >= o) w += y;
                    }
                    s_wsum[lane] = w;
                }
                __syncthreads();
                int incl = v + (wb ? s_wsum[wb - 1] : 0);
                s_pre[tid] = incl;
                int S = x, A = T - incl;
                if (T > 1000 && S > 0 && A < 1000 && A + S > 1000) s_bound = tid;
            }
            __syncthreads();
            int bd = s_bound;
            if (bd >= 0) {
                #pragma unroll
                for (int t = 0; t < 10; t++) {
                    if (ph[t]) {
                        float cf = __uint_as_float((unsigned)(pk[t] >> 12));
                        int bn = min(max((int)(cf * 1024.0f), 0), NBINS - 1);
                        if (bn == bd) {
                            int o = atomicAdd(&s_bbn, 1);
                            if (o < 64) s_bb[o] = pk[t];
                        }
                    }
                }
            }
            __syncthreads();
            int nbb = min(s_bbn, 64);
            bool bbOv = s_bbn > 64;

            // main: one slot per thread
            float psum = 0.0f;
            int s = part * NTHR + tid;
            {
                int c = s >> 7, i = s & (CAPB - 1);
                if (i < s_scnt[c]) {
                    int gb = (b * NC + c) * CAPB + i;
                    unsigned long long mykey = g_kckey[gb];
                    float cf = __uint_as_float((unsigned)(mykey >> 12));
                    int bn = min(max((int)(cf * 1024.0f), 0), NBINS - 1);
                    int incl = s_pre[bn], excl = bn ? s_pre[bn - 1] : 0;
                    int S = incl - excl, A = T - incl;
                    bool keep;
                    if (T <= 1000)          keep = true;
                    else if (A >= 1000)     keep = false;
                    else if (A + S <= 1000) keep = true;
                    else {
                        int rin = 0;
                        if (!bbOv) {
                            for (int q = 0; q < nbb; q++) rin += (s_bb[q] > mykey);
                        } else {  // practically impossible fallback: exact in-bin rank
                            for (int s2 = 0; s2 < SLOTS; s2++) {
                                int c2 = s2 >> 7, i2 = s2 & (CAPB - 1);
                                if (i2 < s_scnt[c2]) {
                                    unsigned long long k2 = g_kckey[(b * NC + c2) * CAPB + i2];
                                    float cf2 = __uint_as_float((unsigned)(k2 >> 12));
                                    int bn2 = min(max((int)(cf2 * 1024.0f), 0), NBINS - 1);
                                    if (bn2 == bn && k2 > mykey) rin++;
                                }
                            }
                        }
                        keep = (A + rin) < 1000;
                    }
                    if (keep) {
                        float4 bxc = g_kcnbox[gb]; float ab = g_kcarea[gb];
                        int Kp = g_pcnt[b * NC + c]; int lb = (b * NC + c) * CAPB;
                        float tmv = 0.0f;
                        for (int mm = 0; mm < Kp; mm++) {
                            float4 pj = g_pnbox[lb + mm];
                            float lx = fmaxf(bxc.x, pj.x), ly = fmaxf(bxc.y, pj.y);
                            float rx = fminf(bxc.z, pj.z), ry = fminf(bxc.w, pj.w);
                            float wv = fmaxf(rx - lx, 0.0f), hv = fmaxf(ry - ly, 0.0f);
                            float inter = wv * hv;
                            float uni = g_parea[lb + mm] + ab - inter;
                            tmv = fmaxf(tmv, __fdiv_rn(inter, uni));
                        }
                        psum = tmv;
                    }
                }
            }
            // block reduce
            {
                #pragma unroll
                for (int o = 16; o; o >>= 1) psum += __shfl_down_sync(FULL, psum, o);
                if (lane == 0) s_red[wb] = psum;
                __syncthreads();
                if (wb == 0) {
                    float v = s_red[lane];
                    #pragma unroll
                    for (int o = 16; o; o >>= 1) v += __shfl_down_sync(FULL, v, o);
                    if (lane == 0) g_part[blockIdx.x] = v;
                }
            }
        }
    }

    // ================= Phase D: last-arriving block computes final scalar ===========
    __syncthreads();
    if (tid == 0) {
        __threadfence();                               // publish this block's g_part
        s_last = (atomicAdd(&g_tick, 1u) == NBLK - 1) ? 1 : 0;
        if (s_last) g_tick = 0;                        // self-reset for next replay
    }
    __syncthreads();
    if (s_last) {
        __threadfence();                               // acquire all g_part writes
        if (tid < BB * NC) s_pre[tid] = g_kccnt[tid];
        float v = (tid < NBLK) ? g_part[tid] : 0.0f;
        #pragma unroll
        for (int o = 16; o; o >>= 1) v += __shfl_down_sync(FULL, v, o);
        if (lane == 0) s_red[wb] = v;
        __syncthreads();
        if (tid == 0) {
            float num = 0.0f;
            #pragma unroll
            for (int w = 0; w < 4; w++) num += s_red[w];   // 128 partials live in warps 0..3
            int den = 0;
            for (int b = 0; b < BB; b++) {
                int t = 0;
                for (int c = 0; c < NC; c++) t += s_pre[b * NC + c];
                den += min(t, 1000);
            }
            out[0] = (den > 0) ? (1.0f - __fdiv_rn(num, (float)den)) : 1.0f;
        }
    }
}

// ---------------- launch ----------------
extern "C" void kernel_launch(void* const* d_in, const int* in_sizes, int n_in,
                              void* d_out, int out_size) {
    const float* c = (const float*)d_in[0];
    const float* p = (const float*)d_in[1];
    float* out = (float*)d_out;
    cudaFuncSetAttribute(k_fused, cudaFuncAttributeMaxDynamicSharedMemorySize, DYN_SMEM);
    k_fused<<<NBLK, NTHR, DYN_SMEM>>>(c, p, out);
}

// round 10
// speedup vs baseline: 1.1011x; 1.0963x over previous
#include <cuda_runtime.h>
#include <stdint.h>

#define BB 4
#define NN 4096
#define NC 80
#define ST 85
#define IOU_TH 0.45f
#define CAPB 128
#define NBINS 1024
#define NBLK 128
#define NTHR 1024
#define TPB 5            // NMS tasks per block (640 / 128)
#define FULL 0xffffffffu
#define SLOTS (NC*CAPB)  // 10240 clean slots per image
#define ROWS_PER_BLK 256
#define TILE_FLOATS (ROWS_PER_BLK*ST)          // 21760
#define TILE_F4 (TILE_FLOATS/4)                // 5440
#define DYN_SMEM (TILE_FLOATS*4)               // 87040 bytes

// ---------------- scratch (device globals; no allocation allowed) ----------------
__device__ unsigned long long g_bkey [2*BB*NC*CAPB]; // (confbits<<20)|((4095-idx)<<8)|slot
__device__ float4             g_bobox[2*BB*NC*CAPB]; // offset boxes (cls*4096 added)
__device__ float4             g_bnbox[2*BB*NC*CAPB]; // normalized boxes (/640)
__device__ int                g_cnt  [2*BB*NC];      // bin counters (consumer-reset)

__device__ int                g_kccnt[BB*NC];
__device__ unsigned long long g_kckey[BB*NC*CAPB];   // (confbits<<12)|(4095-idx)
__device__ float4             g_kcnbox[BB*NC*CAPB];
__device__ float              g_kcarea[BB*NC*CAPB];
__device__ int                g_pcnt [BB*NC];
__device__ float4             g_pnbox[BB*NC*CAPB];
__device__ float              g_parea[BB*NC*CAPB];

__device__ float             g_part[NBLK];
__device__ unsigned          g_bar_cnt;
__device__ volatile unsigned g_bar_gen;
__device__ unsigned          g_tick;                 // phase-D ticket (self-resetting)

__device__ __forceinline__ void grid_barrier() {
    __syncthreads();
    if (threadIdx.x == 0) {
        unsigned gen = g_bar_gen;
        __threadfence();
        if (atomicAdd(&g_bar_cnt, 1u) == NBLK - 1) {
            g_bar_cnt = 0;
            __threadfence();
            g_bar_gen = gen + 1;
        } else {
            while (g_bar_gen == gen) { }   // tight L2 poll, 1 thread/block
        }
        __threadfence();
    }
    __syncthreads();
}

__global__ void __launch_bounds__(NTHR, 1) k_fused(const float* __restrict__ in0,
                                                   const float* __restrict__ in1,
                                                   float* __restrict__ out) {
    extern __shared__ float s_raw[];                 // 256 rows x 85 floats (phase A only)
    __shared__ unsigned long long skey[TPB][CAPB];
    __shared__ float4  s_sbx[TPB][CAPB];
    __shared__ float   s_sar[TPB][CAPB];
    __shared__ uint8_t s_sup[TPB][CAPB];
    __shared__ int   s_pre[NBINS];
    __shared__ float s_red[NTHR];
    __shared__ int   s_scnt[NC];
    __shared__ int   s_wsum[32];
    __shared__ unsigned long long s_bb[64];
    __shared__ int   s_T, s_bound, s_bbn, s_last;

    const int tid  = threadIdx.x;
    const int lane = tid & 31;
    const int wb   = tid >> 5;

    // ================= Phase A: stream tile to smem; 4-lane-per-box decode ==========
    {
        const int set      = blockIdx.x >> 6;            // 0..63 clean, 64..127 patch
        const int tilebase = (blockIdx.x & 63) * ROWS_PER_BLK;
        const float4* src4 = (const float4*)((set ? in1 : in0) + (size_t)tilebase * ST);
        float4* d4 = (float4*)s_raw;

        #pragma unroll
        for (int t = 0; t < 6; t++) {                    // 6*1024 >= 5440
            int i = tid + t * NTHR;
            if (i < TILE_F4) d4[i] = __ldg(src4 + i);
        }
        __syncthreads();

        const int g  = lane >> 2;                        // box group 0..7
        const int lg = lane & 3;                         // lane in group
        const int row = (wb << 3) | g;
        const float* rp = s_raw + row * ST;
        float obj = rp[4];

        float bv = -1e30f; int bc = 0x7fffffff;
        #pragma unroll
        for (int t = 0; t < 20; t++) {
            int c = lg + (t << 2);                       // 20 classes per lane
            float s = rp[5 + c] * obj;                   // ref op order: cls * obj
            if (s > bv) { bv = s; bc = c; }              // strict > keeps first in-lane
        }
        // 2-level xor reduce within the 4-lane group (value desc, index asc)
        #pragma unroll
        for (int o = 1; o <= 2; o <<= 1) {
            float ov = __shfl_xor_sync(FULL, bv, o);
            int   oi = __shfl_xor_sync(FULL, bc, o);
            if (ov > bv || (ov == bv && oi < bc)) { bv = ov; bc = oi; }
        }

        if (lg == 0) {                                   // 8 parallel writers per warp
            int r = tilebase + row;                      // b*NN + n within set
            float th = set ? 0.001f : 0.25f;
            if (obj > th && bv > th) {
                float cx = rp[0], cy = rp[1], w = rp[2], h = rp[3];
                float hw = w * 0.5f, hh = h * 0.5f;
                float x1 = cx - hw, y1 = cy - hh, x2 = cx + hw, y2 = cy + hh;
                float off = (float)bc * 4096.0f;
                int b = r >> 12, idx = r & (NN - 1);
                int bin = (set * BB + b) * NC + bc;
                int slot = atomicAdd(&g_cnt[bin], 1);
                if (slot < CAPB) {
                    int a = bin * CAPB + slot;
                    float4 ob; ob.x = x1 + off; ob.y = y1 + off; ob.z = x2 + off; ob.w = y2 + off;
                    float4 nb; nb.x = __fdiv_rn(x1, 640.0f); nb.y = __fdiv_rn(y1, 640.0f);
                               nb.z = __fdiv_rn(x2, 640.0f); nb.w = __fdiv_rn(y2, 640.0f);
                    g_bobox[a] = ob; g_bnbox[a] = nb;
                    g_bkey [a] = ((unsigned long long)__float_as_uint(bv) << 20)
                               | ((unsigned long long)(4095 - idx) << 8)
                               | (unsigned long long)slot;
                }
            }
        }
    }
    grid_barrier();

    // ================= Phase B: rank-sort + smem-broadcast greedy NMS ===============
    if (wb < TPB) {
        int task = blockIdx.x * TPB + wb;            // 0..639
        int c   = task % NC;
        int sb  = task / NC;
        int set = sb >> 2, b = sb & 3;
        int bin = sb * NC + c;
        int gbase = bin * CAPB;

        int K = min(g_cnt[bin], CAPB);
        if (lane == 0) g_cnt[bin] = 0;

        for (int i = lane; i < K; i += 32) skey[wb][i] = g_bkey[gbase + i];
        __syncwarp();

        // rank-sort: position = count of strictly greater keys (keys unique by idx)
        unsigned long long own[4]; int rnk[4];
        #pragma unroll
        for (int p = 0; p < 4; p++) {
            int pos = p * 32 + lane;
            own[p] = (pos < K) ? skey[wb][pos] : 0ull;
            rnk[p] = 0;
        }
        for (int j = 0; j < K; j++) {
            unsigned long long v = skey[wb][j];      // LDS broadcast, pipelined
            #pragma unroll
            for (int p = 0; p < 4; p++) rnk[p] += (v > own[p]);
        }
        __syncwarp();                                 // all reads done before scatter
        #pragma unroll
        for (int p = 0; p < 4; p++) {
            int pos = p * 32 + lane;
            if (pos < K) skey[wb][rnk[p] & (CAPB - 1)] = own[p];
        }
        __syncwarp();

        // gather sorted boxes into smem; init flags
        for (int i = lane; i < K; i += 32) {
            unsigned long long key = skey[wb][i];
            float4 bo = g_bobox[gbase + (int)(key & (unsigned long long)(CAPB - 1))];
            s_sbx[wb][i] = bo;
            s_sar[wb][i] = (bo.z - bo.x) * (bo.w - bo.y);  // offset-box area (ref rounding)
            s_sup[wb][i] = 0;
        }
        __syncwarp();

        // register copies of owned positions
        float4 bx[4]; float ar[4]; unsigned sup = 0;
        #pragma unroll
        for (int q = 0; q < 4; q++) {
            int pos = q * 32 + lane;
            if (pos < K) { bx[q] = s_sbx[wb][pos]; ar[q] = s_sar[wb][pos]; }
            else         { bx[q] = make_float4(0,0,0,0); ar[q] = 0.f; sup |= 1u << q; }
        }
        __syncwarp();

        // greedy suppression: smem broadcast of box i, flags in smem + register mirror
        for (int i = 0; i < K; i++) {
            if (s_sup[wb][i] == 0) {
                float4 bi = s_sbx[wb][i]; float ai = s_sar[wb][i];  // LDS broadcast
                #pragma unroll
                for (int p = 0; p < 4; p++) {
                    int j = p * 32 + lane;
                    if (j > i && j < K && !((sup >> p) & 1)) {
                        float lx = fmaxf(bi.x, bx[p].x), ly = fmaxf(bi.y, bx[p].y);
                        float rx = fminf(bi.z, bx[p].z), ry = fminf(bi.w, bx[p].w);
                        float wv = fmaxf(rx - lx, 0.0f), hv = fmaxf(ry - ly, 0.0f);
                        float inter = wv * hv;
                        float uni = ai + ar[p] - inter;
                        if (__fdiv_rn(inter, uni) > IOU_TH) { sup |= 1u << p; s_sup[wb][j] = 1; }
                    }
                }
            }
            __syncwarp();
        }

        // ballot-compact kept, in sorted order (deterministic)
        int m = 0;
        #pragma unroll
        for (int q = 0; q < 4; q++) {
            int pos = q * 32 + lane;
            bool kp = (pos < K) && !((sup >> q) & 1);
            unsigned bal = __ballot_sync(FULL, kp);
            if (kp) {
                int o = m + __popc(bal & ((1u << lane) - 1u));
                unsigned long long key = skey[wb][pos];
                int slot = (int)(key & (unsigned long long)(CAPB - 1));
                float4 nb = g_bnbox[gbase + slot];
                float na = (nb.z - nb.x) * (nb.w - nb.y);
                int dst = (b * NC + c) * CAPB + o;
                if (set == 0) {
                    g_kckey [dst] = key >> 8;        // (confbits<<12)|(4095-idx)
                    g_kcnbox[dst] = nb; g_kcarea[dst] = na;
                } else {
                    g_pnbox[dst] = nb; g_parea[dst] = na;
                }
            }
            m += __popc(bal);
        }
        if (lane == 0) { if (set == 0) g_kccnt[b * NC + c] = m; else g_pcnt[b * NC + c] = m; }
    }
    grid_barrier();

    // ================= Phase C: cap@1000 (hist rank) + tm + partials ================
    {
        int b    = blockIdx.x & 3;
        int part = blockIdx.x >> 2;                  // 0..31; only parts 0..9 hold slots

        if (part >= 10) {
            if (tid == 0) g_part[blockIdx.x] = 0.0f; // idle block: contribute zero
        } else {
            if (tid < NC) s_scnt[tid] = g_kccnt[b * NC + tid];
            s_pre[tid] = 0;
            __syncthreads();
            if (tid == 0) {
                int t = 0;
                #pragma unroll
                for (int c = 0; c < NC; c++) t += s_scnt[c];
                s_T = t; s_bound = -1; s_bbn = 0;
            }

            // prefetch this thread's 10 strided slot keys (MLP=10, reused twice)
            unsigned long long pk[10]; bool ph[10];
            #pragma unroll
            for (int t = 0; t < 10; t++) {
                int s = tid + t * NTHR;              // < 10240
                int c = s >> 7, i = s & (CAPB - 1);
                ph[t] = i < s_scnt[c];
                pk[t] = ph[t] ? g_kckey[(b * NC + c) * CAPB + i] : 0ull;
            }
            __syncthreads();
            int T = s_T;

            // histogram
            #pragma unroll
            for (int t = 0; t < 10; t++) {
                if (ph[t]) {
                    float cf = __uint_as_float((unsigned)(pk[t] >> 12));
                    int bn = min(max((int)(cf * 1024.0f), 0), NBINS - 1);
                    atomicAdd(&s_pre[bn], 1);
                }
            }
            __syncthreads();

            // two-level shuffle scan over 1024 bins (1 bin/thread)
            {
                int x = s_pre[tid];
                int v = x;
                #pragma unroll
                for (int o = 1; o < 32; o <<= 1) {
                    int y = __shfl_up_sync(FULL, v, o);
                    if (lane >= o) v += y;
                }
                if (lane == 31) s_wsum[wb] = v;
                __syncthreads();
                if (wb == 0) {
                    int w = s_wsum[lane];
                    #pragma unroll
                    for (int o = 1; o < 32; o <<= 1) {
                        int y = __shfl_up_sync(FULL, w, o);
                        if (lane >= o) w += y;
                    }
                    s_wsum[lane] = w;
                }
                __syncthreads();
                int incl = v + (wb ? s_wsum[wb - 1] : 0);
                s_pre[tid] = incl;
                int S = x, A = T - incl;
                if (T > 1000 && S > 0 && A < 1000 && A + S > 1000) s_bound = tid;
            }
            __syncthreads();
            int bd = s_bound;
            if (bd >= 0) {
                #pragma unroll
                for (int t = 0; t < 10; t++) {
                    if (ph[t]) {
                        float cf = __uint_as_float((unsigned)(pk[t] >> 12));
                        int bn = min(max((int)(cf * 1024.0f), 0), NBINS - 1);
                        if (bn == bd) {
                            int o = atomicAdd(&s_bbn, 1);
                            if (o < 64) s_bb[o] = pk[t];
                        }
                    }
                }
            }
            __syncthreads();
            int nbb = min(s_bbn, 64);
            bool bbOv = s_bbn > 64;

            // main: one slot per thread
            float psum = 0.0f;
            int s = part * NTHR + tid;
            {
                int c = s >> 7, i = s & (CAPB - 1);
                if (i < s_scnt[c]) {
                    int gb = (b * NC + c) * CAPB + i;
                    unsigned long long mykey = g_kckey[gb];
                    float cf = __uint_as_float((unsigned)(mykey >> 12));
                    int bn = min(max((int)(cf * 1024.0f), 0), NBINS - 1);
                    int incl = s_pre[bn], excl = bn ? s_pre[bn - 1] : 0;
                    int S = incl - excl, A = T - incl;
                    bool keep;
                    if (T <= 1000)          keep = true;
                    else if (A >= 1000)     keep = false;
                    else if (A + S <= 1000) keep = true;
                    else {
                        int rin = 0;
                        if (!bbOv) {
                            for (int q = 0; q < nbb; q++) rin += (s_bb[q] > mykey);
                        } else {  // practically impossible fallback: exact in-bin rank
                            for (int s2 = 0; s2 < SLOTS; s2++) {
                                int c2 = s2 >> 7, i2 = s2 & (CAPB - 1);
                                if (i2 < s_scnt[c2]) {
                                    unsigned long long k2 = g_kckey[(b * NC + c2) * CAPB + i2];
                                    float cf2 = __uint_as_float((unsigned)(k2 >> 12));
                                    int bn2 = min(max((int)(cf2 * 1024.0f), 0), NBINS - 1);
                                    if (bn2 == bn && k2 > mykey) rin++;
                                }
                            }
                        }
                        keep = (A + rin) < 1000;
                    }
                    if (keep) {
                        float4 bxc = g_kcnbox[gb]; float ab = g_kcarea[gb];
                        int Kp = g_pcnt[b * NC + c]; int lb = (b * NC + c) * CAPB;
                        float tmv = 0.0f;
                        for (int mm = 0; mm < Kp; mm++) {
                            float4 pj = g_pnbox[lb + mm];
                            float lx = fmaxf(bxc.x, pj.x), ly = fmaxf(bxc.y, pj.y);
                            float rx = fminf(bxc.z, pj.z), ry = fminf(bxc.w, pj.w);
                            float wv = fmaxf(rx - lx, 0.0f), hv = fmaxf(ry - ly, 0.0f);
                            float inter = wv * hv;
                            float uni = g_parea[lb + mm] + ab - inter;
                            tmv = fmaxf(tmv, __fdiv_rn(inter, uni));
                        }
                        psum = tmv;
                    }
                }
            }
            // block reduce
            {
                #pragma unroll
                for (int o = 16; o; o >>= 1) psum += __shfl_down_sync(FULL, psum, o);
                if (lane == 0) s_red[wb] = psum;
                __syncthreads();
                if (wb == 0) {
                    float v = s_red[lane];
                    #pragma unroll
                    for (int o = 16; o; o >>= 1) v += __shfl_down_sync(FULL, v, o);
                    if (lane == 0) g_part[blockIdx.x] = v;
                }
            }
        }
    }

    // ================= Phase D: last-arriving block computes final scalar ===========
    __syncthreads();
    if (tid == 0) {
        __threadfence();                               // publish this block's g_part
        s_last = (atomicAdd(&g_tick, 1u) == NBLK - 1) ? 1 : 0;
        if (s_last) g_tick = 0;                        // self-reset for next replay
    }
    __syncthreads();
    if (s_last) {
        __threadfence();                               // acquire all g_part writes
        if (tid < BB * NC) s_pre[tid] = g_kccnt[tid];
        float v = (tid < NBLK) ? g_part[tid] : 0.0f;
        #pragma unroll
        for (int o = 16; o; o >>= 1) v += __shfl_down_sync(FULL, v, o);
        if (lane == 0) s_red[wb] = v;
        __syncthreads();
        if (tid == 0) {
            float num = 0.0f;
            #pragma unroll
            for (int w = 0; w < 4; w++) num += s_red[w];   // 128 partials live in warps 0..3
            int den = 0;
            for (int b = 0; b < BB; b++) {
                int t = 0;
                for (int c = 0; c < NC; c++) t += s_pre[b * NC + c];
                den += min(t, 1000);
            }
            out[0] = (den > 0) ? (1.0f - __fdiv_rn(num, (float)den)) : 1.0f;
        }
    }
}

// ---------------- launch ----------------
extern "C" void kernel_launch(void* const* d_in, const int* in_sizes, int n_in,
                              void* d_out, int out_size) {
    const float* c = (const float*)d_in[0];
    const float* p = (const float*)d_in[1];
    float* out = (float*)d_out;
    cudaFuncSetAttribute(k_fused, cudaFuncAttributeMaxDynamicSharedMemorySize, DYN_SMEM);
    k_fused<<<NBLK, NTHR, DYN_SMEM>>>(c, p, out);
}

// round 11
// speedup vs baseline: 1.1016x; 1.0004x over previous
#include <cuda_runtime.h>
#include <stdint.h>

#define BB 4
#define NN 4096
#define NC 80
#define ST 85
#define IOU_TH 0.45f
#define CAPB 128
#define NBINS 1024
#define NBLK 128
#define NTHR 1024
#define TPB 5            // NMS tasks per block (640 / 128)
#define FULL 0xffffffffu
#define SLOTS (NC*CAPB)  // 10240 clean slots per image
#define ROWS_PER_BLK 256
#define TILE_FLOATS (ROWS_PER_BLK*ST)          // 21760
#define TILE_F4 (TILE_FLOATS/4)                // 5440
#define DYN_SMEM (TILE_FLOATS*4)               // 87040 bytes

// ---------------- scratch (device globals; no allocation allowed) ----------------
__device__ unsigned long long g_bkey [2*BB*NC*CAPB]; // (confbits<<20)|((4095-idx)<<8)|slot
__device__ float4             g_bobox[2*BB*NC*CAPB]; // offset boxes (cls*4096 added)
__device__ float4             g_bnbox[2*BB*NC*CAPB]; // normalized boxes (/640)
__device__ int                g_cnt  [2*BB*NC];      // bin counters (consumer-reset)

__device__ int                g_kccnt[BB*NC];
__device__ unsigned long long g_kckey[BB*NC*CAPB];   // (confbits<<12)|(4095-idx)
__device__ float4             g_kcnbox[BB*NC*CAPB];
__device__ float              g_kcarea[BB*NC*CAPB];
__device__ int                g_pcnt [BB*NC];
__device__ float4             g_pnbox[BB*NC*CAPB];
__device__ float              g_parea[BB*NC*CAPB];

__device__ float             g_part[NBLK];
__device__ unsigned          g_bar_cnt;
__device__ volatile unsigned g_bar_gen;
__device__ unsigned          g_tick;                 // phase-D ticket (self-resetting)

__device__ __forceinline__ void grid_barrier() {
    __syncthreads();
    if (threadIdx.x == 0) {
        unsigned gen = g_bar_gen;
        __threadfence();
        if (atomicAdd(&g_bar_cnt, 1u) == NBLK - 1) {
            g_bar_cnt = 0;
            __threadfence();
            g_bar_gen = gen + 1;
        } else {
            while (g_bar_gen == gen) { }   // tight L2 poll, 1 thread/block
        }
        __threadfence();
    }
    __syncthreads();
}

__global__ void __launch_bounds__(NTHR, 1) k_fused(const float* __restrict__ in0,
                                                   const float* __restrict__ in1,
                                                   float* __restrict__ out) {
    extern __shared__ float s_raw[];                 // 256 rows x 85 floats (phase A only)
    __shared__ unsigned long long skey[TPB][CAPB];
    __shared__ float4  s_sbx[TPB][CAPB];
    __shared__ float   s_sar[TPB][CAPB];
    __shared__ int   s_pre[NBINS];
    __shared__ float s_red[NTHR];
    __shared__ int   s_scnt[NC];
    __shared__ int   s_wsum[32];
    __shared__ unsigned long long s_bb[64];
    __shared__ int   s_T, s_bound, s_bbn, s_last;

    const int tid  = threadIdx.x;
    const int lane = tid & 31;
    const int wb   = tid >> 5;

    // ================= Phase A: stream tile to smem; 4-lane-per-box decode ==========
    {
        const int set      = blockIdx.x >> 6;            // 0..63 clean, 64..127 patch
        const int tilebase = (blockIdx.x & 63) * ROWS_PER_BLK;
        const float4* src4 = (const float4*)((set ? in1 : in0) + (size_t)tilebase * ST);
        float4* d4 = (float4*)s_raw;

        #pragma unroll
        for (int t = 0; t < 6; t++) {                    // 6*1024 >= 5440
            int i = tid + t * NTHR;
            if (i < TILE_F4) d4[i] = __ldg(src4 + i);
        }
        __syncthreads();

        const int g  = lane >> 2;                        // box group 0..7
        const int lg = lane & 3;                         // lane in group
        const int row = (wb << 3) | g;
        const float* rp = s_raw + row * ST;
        float obj = rp[4];

        float bv = -1e30f; int bc = 0x7fffffff;
        #pragma unroll
        for (int t = 0; t < 20; t++) {
            int c = lg + (t << 2);                       // 20 classes per lane
            float s = rp[5 + c] * obj;                   // ref op order: cls * obj
            if (s > bv) { bv = s; bc = c; }              // strict > keeps first in-lane
        }
        // 2-level xor reduce within the 4-lane group (value desc, index asc)
        #pragma unroll
        for (int o = 1; o <= 2; o <<= 1) {
            float ov = __shfl_xor_sync(FULL, bv, o);
            int   oi = __shfl_xor_sync(FULL, bc, o);
            if (ov > bv || (ov == bv && oi < bc)) { bv = ov; bc = oi; }
        }

        if (lg == 0) {                                   // 8 parallel writers per warp
            int r = tilebase + row;                      // b*NN + n within set
            float th = set ? 0.001f : 0.25f;
            if (obj > th && bv > th) {
                float cx = rp[0], cy = rp[1], w = rp[2], h = rp[3];
                float hw = w * 0.5f, hh = h * 0.5f;
                float x1 = cx - hw, y1 = cy - hh, x2 = cx + hw, y2 = cy + hh;
                float off = (float)bc * 4096.0f;
                int b = r >> 12, idx = r & (NN - 1);
                int bin = (set * BB + b) * NC + bc;
                int slot = atomicAdd(&g_cnt[bin], 1);
                if (slot < CAPB) {
                    int a = bin * CAPB + slot;
                    float4 ob; ob.x = x1 + off; ob.y = y1 + off; ob.z = x2 + off; ob.w = y2 + off;
                    float4 nb; nb.x = __fdiv_rn(x1, 640.0f); nb.y = __fdiv_rn(y1, 640.0f);
                               nb.z = __fdiv_rn(x2, 640.0f); nb.w = __fdiv_rn(y2, 640.0f);
                    g_bobox[a] = ob; g_bnbox[a] = nb;
                    g_bkey [a] = ((unsigned long long)__float_as_uint(bv) << 20)
                               | ((unsigned long long)(4095 - idx) << 8)
                               | (unsigned long long)slot;
                }
            }
        }
    }
    grid_barrier();

    // ================= Phase B: rank-sort + register-flag greedy NMS ================
    if (wb < TPB) {
        int task = blockIdx.x * TPB + wb;            // 0..639
        int c   = task % NC;
        int sb  = task / NC;
        int set = sb >> 2, b = sb & 3;
        int bin = sb * NC + c;
        int gbase = bin * CAPB;

        int K = min(g_cnt[bin], CAPB);
        if (lane == 0) g_cnt[bin] = 0;

        for (int i = lane; i < K; i += 32) skey[wb][i] = g_bkey[gbase + i];
        __syncwarp();

        // rank-sort: position = count of strictly greater keys (keys unique by idx)
        unsigned long long own[4]; int rnk[4];
        #pragma unroll
        for (int p = 0; p < 4; p++) {
            int pos = p * 32 + lane;
            own[p] = (pos < K) ? skey[wb][pos] : 0ull;
            rnk[p] = 0;
        }
        for (int j = 0; j < K; j++) {
            unsigned long long v = skey[wb][j];      // LDS broadcast, pipelined
            #pragma unroll
            for (int p = 0; p < 4; p++) rnk[p] += (v > own[p]);
        }
        __syncwarp();                                 // all reads done before scatter
        #pragma unroll
        for (int p = 0; p < 4; p++) {
            int pos = p * 32 + lane;
            if (pos < K) skey[wb][rnk[p] & (CAPB - 1)] = own[p];
        }
        __syncwarp();

        // gather sorted boxes into smem
        for (int i = lane; i < K; i += 32) {
            unsigned long long key = skey[wb][i];
            float4 bo = g_bobox[gbase + (int)(key & (unsigned long long)(CAPB - 1))];
            s_sbx[wb][i] = bo;
            s_sar[wb][i] = (bo.z - bo.x) * (bo.w - bo.y);  // offset-box area (ref rounding)
        }
        __syncwarp();

        // register copies of owned positions; pad bits pre-suppressed
        float4 bx[4]; float ar[4]; unsigned sup = 0;
        #pragma unroll
        for (int q = 0; q < 4; q++) {
            int pos = q * 32 + lane;
            if (pos < K) { bx[q] = s_sbx[wb][pos]; ar[q] = s_sar[wb][pos]; }
            else         { bx[q] = make_float4(0,0,0,0); ar[q] = 0.f; sup |= 1u << q; }
        }
        __syncwarp();

        // greedy suppression: flag of box i fetched via ONE shuffle from owner lane;
        // no smem flag traffic, no per-iteration syncwarp (shfl_sync converges warp)
        if (K > 0) {
            float4 bi = s_sbx[wb][0]; float ai = s_sar[wb][0];
            for (int i = 0; i < K; i++) {
                float4 bnx = bi; float anx = ai;
                if (i + 1 < K) { bnx = s_sbx[wb][i + 1]; anx = s_sar[wb][i + 1]; } // prefetch
                unsigned supo = __shfl_sync(FULL, sup, i & 31);
                if (!((supo >> (i >> 5)) & 1u)) {
                    #pragma unroll
                    for (int p = 0; p < 4; p++) {
                        int j = p * 32 + lane;
                        if (j > i && !((sup >> p) & 1u)) {       // pad bits already set
                            float lx = fmaxf(bi.x, bx[p].x), ly = fmaxf(bi.y, bx[p].y);
                            float rx = fminf(bi.z, bx[p].z), ry = fminf(bi.w, bx[p].w);
                            float wv = fmaxf(rx - lx, 0.0f), hv = fmaxf(ry - ly, 0.0f);
                            float inter = wv * hv;
                            float uni = ai + ar[p] - inter;
                            if (__fdiv_rn(inter, uni) > IOU_TH) sup |= 1u << p;
                        }
                    }
                }
                bi = bnx; ai = anx;
            }
        }

        // ballot-compact kept, in sorted order (deterministic)
        int m = 0;
        #pragma unroll
        for (int q = 0; q < 4; q++) {
            int pos = q * 32 + lane;
            bool kp = (pos < K) && !((sup >> q) & 1);
            unsigned bal = __ballot_sync(FULL, kp);
            if (kp) {
                int o = m + __popc(bal & ((1u << lane) - 1u));
                unsigned long long key = skey[wb][pos];
                int slot = (int)(key & (unsigned long long)(CAPB - 1));
                float4 nb = g_bnbox[gbase + slot];
                float na = (nb.z - nb.x) * (nb.w - nb.y);
                int dst = (b * NC + c) * CAPB + o;
                if (set == 0) {
                    g_kckey [dst] = key >> 8;        // (confbits<<12)|(4095-idx)
                    g_kcnbox[dst] = nb; g_kcarea[dst] = na;
                } else {
                    g_pnbox[dst] = nb; g_parea[dst] = na;
                }
            }
            m += __popc(bal);
        }
        if (lane == 0) { if (set == 0) g_kccnt[b * NC + c] = m; else g_pcnt[b * NC + c] = m; }
    }
    grid_barrier();

    // ================= Phase C: cap@1000 (hist rank) + tm + partials ================
    {
        int b    = blockIdx.x & 3;
        int part = blockIdx.x >> 2;                  // 0..31; only parts 0..9 hold slots

        if (part >= 10) {
            if (tid == 0) g_part[blockIdx.x] = 0.0f; // idle block: contribute zero
        } else {
            if (tid < NC) s_scnt[tid] = g_kccnt[b * NC + tid];
            s_pre[tid] = 0;
            __syncthreads();
            if (tid == 0) {
                int t = 0;
                #pragma unroll
                for (int c = 0; c < NC; c++) t += s_scnt[c];
                s_T = t; s_bound = -1; s_bbn = 0;
            }

            // prefetch this thread's 10 strided slot keys (MLP=10, reused twice)
            unsigned long long pk[10]; bool ph[10];
            #pragma unroll
            for (int t = 0; t < 10; t++) {
                int s = tid + t * NTHR;              // < 10240
                int c = s >> 7, i = s & (CAPB - 1);
                ph[t] = i < s_scnt[c];
                pk[t] = ph[t] ? g_kckey[(b * NC + c) * CAPB + i] : 0ull;
            }
            __syncthreads();
            int T = s_T;

            // histogram
            #pragma unroll
            for (int t = 0; t < 10; t++) {
                if (ph[t]) {
                    float cf = __uint_as_float((unsigned)(pk[t] >> 12));
                    int bn = min(max((int)(cf * 1024.0f), 0), NBINS - 1);
                    atomicAdd(&s_pre[bn], 1);
                }
            }
            __syncthreads();

            // two-level shuffle scan over 1024 bins (1 bin/thread)
            {
                int x = s_pre[tid];
                int v = x;
                #pragma unroll
                for (int o = 1; o < 32; o <<= 1) {
                    int y = __shfl_up_sync(FULL, v, o);
                    if (lane >= o) v += y;
                }
                if (lane == 31) s_wsum[wb] = v;
                __syncthreads();
                if (wb == 0) {
                    int w = s_wsum[lane];
                    #pragma unroll
                    for (int o = 1; o < 32; o <<= 1) {
                        int y = __shfl_up_sync(FULL, w, o);
                        if (lane >= o) w += y;
                    }
                    s_wsum[lane] = w;
                }
                __syncthreads();
                int incl = v + (wb ? s_wsum[wb - 1] : 0);
                s_pre[tid] = incl;
                int S = x, A = T - incl;
                if (T > 1000 && S > 0 && A < 1000 && A + S > 1000) s_bound = tid;
            }
            __syncthreads();
            int bd = s_bound;
            if (bd >= 0) {
                #pragma unroll
                for (int t = 0; t < 10; t++) {
                    if (ph[t]) {
                        float cf = __uint_as_float((unsigned)(pk[t] >> 12));
                        int bn = min(max((int)(cf * 1024.0f), 0), NBINS - 1);
                        if (bn == bd) {
                            int o = atomicAdd(&s_bbn, 1);
                            if (o < 64) s_bb[o] = pk[t];
                        }
                    }
                }
            }
            __syncthreads();
            int nbb = min(s_bbn, 64);
            bool bbOv = s_bbn > 64;

            // main: one slot per thread
            float psum = 0.0f;
            int s = part * NTHR + tid;
            {
                int c = s >> 7, i = s & (CAPB - 1);
                if (i < s_scnt[c]) {
                    int gb = (b * NC + c) * CAPB + i;
                    unsigned long long mykey = g_kckey[gb];
                    float cf = __uint_as_float((unsigned)(mykey >> 12));
                    int bn = min(max((int)(cf * 1024.0f), 0), NBINS - 1);
                    int incl = s_pre[bn], excl = bn ? s_pre[bn - 1] : 0;
                    int S = incl - excl, A = T - incl;
                    bool keep;
                    if (T <= 1000)          keep = true;
                    else if (A >= 1000)     keep = false;
                    else if (A + S <= 1000) keep = true;
                    else {
                        int rin = 0;
                        if (!bbOv) {
                            for (int q = 0; q < nbb; q++) rin += (s_bb[q] > mykey);
                        } else {  // practically impossible fallback: exact in-bin rank
                            for (int s2 = 0; s2 < SLOTS; s2++) {
                                int c2 = s2 >> 7, i2 = s2 & (CAPB - 1);
                                if (i2 < s_scnt[c2]) {
                                    unsigned long long k2 = g_kckey[(b * NC + c2) * CAPB + i2];
                                    float cf2 = __uint_as_float((unsigned)(k2 >> 12));
                                    int bn2 = min(max((int)(cf2 * 1024.0f), 0), NBINS - 1);
                                    if (bn2 == bn && k2 > mykey) rin++;
                                }
                            }
                        }
                        keep = (A + rin) < 1000;
                    }
                    if (keep) {
                        float4 bxc = g_kcnbox[gb]; float ab = g_kcarea[gb];
                        int Kp = g_pcnt[b * NC + c]; int lb = (b * NC + c) * CAPB;
                        float tmv = 0.0f;
                        #pragma unroll 4
                        for (int mm = 0; mm < Kp; mm++) {
                            float4 pj = g_pnbox[lb + mm];
                            float lx = fmaxf(bxc.x, pj.x), ly = fmaxf(bxc.y, pj.y);
                            float rx = fminf(bxc.z, pj.z), ry = fminf(bxc.w, pj.w);
                            float wv = fmaxf(rx - lx, 0.0f), hv = fmaxf(ry - ly, 0.0f);
                            float inter = wv * hv;
                            float uni = g_parea[lb + mm] + ab - inter;
                            tmv = fmaxf(tmv, __fdiv_rn(inter, uni));
                        }
                        psum = tmv;
                    }
                }
            }
            // block reduce
            {
                #pragma unroll
                for (int o = 16; o; o >>= 1) psum += __shfl_down_sync(FULL, psum, o);
                if (lane == 0) s_red[wb] = psum;
                __syncthreads();
                if (wb == 0) {
                    float v = s_red[lane];
                    #pragma unroll
                    for (int o = 16; o; o >>= 1) v += __shfl_down_sync(FULL, v, o);
                    if (lane == 0) g_part[blockIdx.x] = v;
                }
            }
        }
    }

    // ================= Phase D: last-arriving block computes final scalar ===========
    __syncthreads();
    if (tid == 0) {
        __threadfence();                               // publish this block's g_part
        s_last = (atomicAdd(&g_tick, 1u) == NBLK - 1) ? 1 : 0;
        if (s_last) g_tick = 0;                        // self-reset for next replay
    }
    __syncthreads();
    if (s_last) {
        __threadfence();                               // acquire all g_part writes
        if (tid < BB * NC) s_pre[tid] = g_kccnt[tid];
        float v = (tid < NBLK) ? g_part[tid] : 0.0f;
        #pragma unroll
        for (int o = 16; o; o >>= 1) v += __shfl_down_sync(FULL, v, o);
        if (lane == 0) s_red[wb] = v;
        __syncthreads();
        if (tid == 0) {
            float num = 0.0f;
            #pragma unroll
            for (int w = 0; w < 4; w++) num += s_red[w];   // 128 partials live in warps 0..3
            int den = 0;
            for (int b = 0; b < BB; b++) {
                int t = 0;
                for (int c = 0; c < NC; c++) t += s_pre[b * NC + c];
                den += min(t, 1000);
            }
            out[0] = (den > 0) ? (1.0f - __fdiv_rn(num, (float)den)) : 1.0f;
        }
    }
}

// ---------------- launch ----------------
extern "C" void kernel_launch(void* const* d_in, const int* in_sizes, int n_in,
                              void* d_out, int out_size) {
    const float* c = (const float*)d_in[0];
    const float* p = (const float*)d_in[1];
    float* out = (float*)d_out;
    cudaFuncSetAttribute(k_fused, cudaFuncAttributeMaxDynamicSharedMemorySize, DYN_SMEM);
    k_fused<<<NBLK, NTHR, DYN_SMEM>>>(c, p, out);
}